// round 1
// baseline (speedup 1.0000x reference)
#include <cuda_runtime.h>

#define CIN   80
#define COUT  32
#define BATCH 8
#define HH    160
#define WW    320
#define DD    48
#define HW    (HH*WW)      // 51200
#define RSTR  376          // padded R row stride (floats)

typedef unsigned long long ull;

// Scratch for preconv outputs: [B][32][H][W] each
__device__ float g_featL[BATCH*COUT*HW];
__device__ float g_featR[BATCH*COUT*HW];

__device__ __forceinline__ ull fma2(ull a, ull b, ull c) {
    ull d;
    asm("fma.rn.f32x2 %0, %1, %2, %3;" : "=l"(d) : "l"(a), "l"(b), "l"(c));
    return d;
}
__device__ __forceinline__ ull pack2(float lo, float hi) {
    ull d;
    asm("mov.b64 %0, {%1, %2};" : "=l"(d) : "f"(lo), "f"(hi));
    return d;
}

// ---------------------------------------------------------------------------
// Kernel 1: fused ReLU + BN(eval) + 1x1 conv (80 -> 32), both images.
// Each thread computes 2 adjacent-w pixels packed in f32x2; 32 accumulators.
// W' (BN-folded, splatted to both halves) lives in smem, broadcast LDS.64.
// ---------------------------------------------------------------------------
__global__ __launch_bounds__(256) void preconv_kernel(
    const float* __restrict__ inL, const float* __restrict__ inR,
    const float* __restrict__ bn_g, const float* __restrict__ bn_b,
    const float* __restrict__ bn_m, const float* __restrict__ bn_v,
    const float* __restrict__ cw,   const float* __restrict__ cb)
{
    __shared__ float s_scale[CIN];
    __shared__ float s_shift[CIN];
    __shared__ ull   sW[CIN*COUT];
    __shared__ ull   sB[COUT];

    int tid = threadIdx.x;
    if (tid < CIN) {
        float sc = bn_g[tid] * rsqrtf(bn_v[tid] + 1e-5f);
        s_scale[tid] = sc;
        s_shift[tid] = bn_b[tid] - bn_m[tid] * sc;
    }
    __syncthreads();
    for (int idx = tid; idx < CIN*COUT; idx += 256) {
        int c = idx >> 5, o = idx & 31;
        float wv = cw[o*CIN + c] * s_scale[c];
        sW[c*COUT + o] = pack2(wv, wv);
    }
    if (tid < COUT) {
        float s = cb[tid];
        #pragma unroll 4
        for (int c = 0; c < CIN; c++) s += cw[tid*CIN + c] * s_shift[c];
        sB[tid] = pack2(s, s);
    }
    __syncthreads();

    const float* in  = blockIdx.y ? inR : inL;
    float*       outp = blockIdx.y ? g_featR : g_featL;

    int t = blockIdx.x * 256 + tid;        // pixel-pair index, total 204800
    if (t >= BATCH*HH*(WW/2)) return;
    int wp   = t % (WW/2);
    int rest = t / (WW/2);
    int h    = rest % HH;
    int b    = rest / HH;
    long inbase = (long)b * CIN * HW + (long)h * WW + wp*2;

    ull acc[COUT];
    #pragma unroll
    for (int o = 0; o < COUT; o++) acc[o] = sB[o];

    #pragma unroll 4
    for (int c = 0; c < CIN; c++) {
        float2 x = *(const float2*)(in + inbase + (long)c*HW);
        ull xp = pack2(fmaxf(x.x, 0.f), fmaxf(x.y, 0.f));
        const ull* wr = &sW[c*COUT];
        #pragma unroll
        for (int o = 0; o < COUT; o++) acc[o] = fma2(xp, wr[o], acc[o]);
    }

    long obase = (long)b * COUT * HW + (long)h * WW + wp*2;
    #pragma unroll
    for (int o = 0; o < COUT; o++)
        *(ull*)(outp + obase + (long)o*HW) = acc[o];
}

// ---------------------------------------------------------------------------
// Kernel 2: correlation volume. One block per (b,h) row.
// smem: Ls[32][320]; RA[32][376] (front-padded 48 zeros), RB = RA shifted by 1
// so that every (R[w-i], R[w+1-i]) pair is an ALIGNED LDS.64 for any i parity.
// Lanes are consecutive w-pairs -> 8B lane stride -> conflict-free smem.
// Thread tile: 1 w-pair x 12 disparities, f32x2 accumulate, 2 tiles/thread.
// ---------------------------------------------------------------------------
__global__ __launch_bounds__(320) void corr_kernel(float* __restrict__ out)
{
    extern __shared__ float sm[];
    float* Ls = sm;                    // COUT*WW
    float* RA = sm + COUT*WW;          // COUT*RSTR
    float* RB = RA + COUT*RSTR;        // COUT*RSTR

    int tid = threadIdx.x;
    int bh  = blockIdx.x;
    int h   = bh % HH, b = bh / HH;
    long rowbase = (long)b * COUT * HW + (long)h * WW;   // + c*HW + w

    // Fill Ls with float4 loads
    for (int idx = tid; idx < COUT*(WW/4); idx += 320) {
        int c  = idx / (WW/4);
        int w4 = (idx % (WW/4)) * 4;
        *(float4*)&Ls[c*WW + w4] = *(const float4*)&g_featL[rowbase + (long)c*HW + w4];
    }
    // Fill RA (zero-padded: jj in [48,368) holds R[jj-48])
    for (int idx = tid; idx < COUT*RSTR; idx += 320) {
        int c = idx / RSTR, jj = idx % RSTR;
        int wA = jj - 48;
        RA[idx] = (wA >= 0 && wA < WW) ? g_featR[rowbase + (long)c*HW + wA] : 0.f;
    }
    __syncthreads();
    // RB[j] = RA[j+1] (shift-by-one copy for odd-parity pairs)
    for (int idx = tid; idx < COUT*RSTR; idx += 320) {
        int jj = idx % RSTR;
        RB[idx] = (jj < RSTR-1) ? RA[idx + 1] : 0.f;
    }
    __syncthreads();

    for (int T = tid; T < 640; T += 320) {
        int wp = T % 160;          // lanes consecutive in wp -> conflict-free
        int ig = T / 160;          // 0..3
        int i0 = ig * 12;
        int w0 = wp * 2;

        ull acc[12];
        #pragma unroll
        for (int di = 0; di < 12; di++) acc[di] = 0ULL;

        #pragma unroll 2
        for (int c = 0; c < COUT; c++) {
            ull Lp = *(const ull*)&Ls[c*WW + w0];
            const float* ra = &RA[c*RSTR + (w0 - i0 + 48)];
            const float* rb = &RB[c*RSTR + (w0 - i0 + 47)];
            #pragma unroll
            for (int di = 0; di < 12; di++) {
                // i = i0+di; even di -> RA at (w0-i+48) [even], odd -> RB at (w0-i+47) [even]
                const float* src = (di & 1) ? (rb - di) : (ra - di);
                acc[di] = fma2(Lp, *(const ull*)src, acc[di]);
            }
        }

        long ob = ((long)(b*DD + i0) * HH + h) * WW + w0;
        #pragma unroll
        for (int di = 0; di < 12; di++) {
            float2 v = *(float2*)&acc[di];
            v.x *= 0.03125f;  // 1/32 mean
            v.y *= 0.03125f;
            *(float2*)&out[ob + (long)di*HW] = v;
        }
    }
}

// ---------------------------------------------------------------------------
extern "C" void kernel_launch(void* const* d_in, const int* in_sizes, int n_in,
                              void* d_out, int out_size)
{
    const float* fL = (const float*)d_in[0];
    const float* fR = (const float*)d_in[1];
    const float* bg = (const float*)d_in[2];
    const float* bb = (const float*)d_in[3];
    const float* bm = (const float*)d_in[4];
    const float* bv = (const float*)d_in[5];
    const float* cw = (const float*)d_in[6];
    const float* cb = (const float*)d_in[7];
    float* out = (float*)d_out;

    static bool attr_done = false;
    if (!attr_done) {
        cudaFuncSetAttribute(corr_kernel, cudaFuncAttributeMaxDynamicSharedMemorySize,
                             (COUT*WW + 2*COUT*RSTR) * (int)sizeof(float));
        attr_done = true;
    }

    dim3 grid1(800, 2);
    preconv_kernel<<<grid1, 256>>>(fL, fR, bg, bb, bm, bv, cw, cb);

    int smem = (COUT*WW + 2*COUT*RSTR) * (int)sizeof(float);  // 137216 B
    corr_kernel<<<BATCH*HH, 320, smem>>>(out);
}

// round 2
// speedup vs baseline: 1.2196x; 1.2196x over previous
#include <cuda_runtime.h>

#define CIN   80
#define COUT  32
#define BATCH 8
#define HH    160
#define WW    320
#define DD    48
#define HW    (HH*WW)      // 51200
#define RSTR  376          // padded R row stride (floats): 48 zero + 320 + 8

typedef unsigned long long ull;

__device__ __forceinline__ ull fma2(ull a, ull b, ull c) {
    ull d;
    asm("fma.rn.f32x2 %0, %1, %2, %3;" : "=l"(d) : "l"(a), "l"(b), "l"(c));
    return d;
}
__device__ __forceinline__ ull pack2(float lo, float hi) {
    ull d;
    asm("mov.b64 %0, {%1, %2};" : "=l"(d) : "f"(lo), "f"(hi));
    return d;
}

// Fused kernel: one block per (b,h) row.
//  Phase 0: fold BN into conv weights (smem), zero R pad.
//  Phase 1: preconv (relu+bn+1x1 conv, 80->32) for both images of this row,
//           register-tiled 4 pixel-pairs x 8 outputs, results -> smem.
//  Phase 2: 48-disparity correlation from smem, register tile 1 pair x 12 d,
//           odd-disparity operand pairs assembled in registers (no RB copy).
//
// smem: sW (2560 ull, splatted weights) | sB (32 ull) | Ls[32][320] | RA[32][376]
//   = 20480 + 256 + 40960 + 48128 = 109824 B  -> 2 blocks/SM.
__global__ __launch_bounds__(320, 2) void fused_kernel(
    const float* __restrict__ inL, const float* __restrict__ inR,
    const float* __restrict__ bg,  const float* __restrict__ bb,
    const float* __restrict__ bm,  const float* __restrict__ bv,
    const float* __restrict__ cw,  const float* __restrict__ cb,
    float* __restrict__ out)
{
    extern __shared__ char smraw[];
    ull*   sW = (ull*)smraw;              // [80][32]
    ull*   sB = sW + 2560;                // [32]
    float* Ls = (float*)(sB + 32);        // [32][320]
    float* RA = Ls + 32*WW;               // [32][376], RA[o][j] = featR[o][j-48]

    const int tid = threadIdx.x;

    // ---- Phase 0: weight folding + R pad zeroing ----
    for (int idx = tid; idx < CIN*COUT; idx += 320) {
        int c = idx >> 5, o = idx & 31;
        float sc = bg[c] * rsqrtf(bv[c] + 1e-5f);
        float wv = cw[o*CIN + c] * sc;
        sW[idx] = pack2(wv, wv);
    }
    if (tid < COUT) {
        float s = cb[tid];
        for (int c = 0; c < CIN; c++) {
            float sc = bg[c] * rsqrtf(bv[c] + 1e-5f);
            s += cw[tid*CIN + c] * (bb[c] - bm[c]*sc);
        }
        sB[tid] = pack2(s, s);
    }
    for (int i = tid; i < 32*RSTR/2; i += 320) ((ull*)RA)[i] = 0ULL;
    __syncthreads();

    const int bh = blockIdx.x;
    const int h  = bh % HH, b = bh / HH;

    // ---- Phase 1: preconv, 4 pairs x 8 outputs per thread ----
    {
        const int pg = tid % 80;      // pair-group: lanes consecutive -> coalesced
        const int og = tid / 80;      // output group 0..3 -> outputs og*8..og*8+7
        const long base = (long)b * CIN * HW + (long)h * WW;
        // pairs k: k0 = L w0=2pg, k1 = L w0=2pg+160, k2 = R 2pg, k3 = R 2pg+160
        const float* p0 = inL + base + 2*pg;
        const float* p1 = inL + base + 2*pg + 160;
        const float* p2 = inR + base + 2*pg;
        const float* p3 = inR + base + 2*pg + 160;

        ull acc[32];
        #pragma unroll
        for (int i = 0; i < 32; i++) acc[i] = sB[og*8 + (i & 7)];

        for (int c = 0; c < CIN; c++) {
            float2 a0 = *(const float2*)(p0 + (long)c*HW);
            float2 a1 = *(const float2*)(p1 + (long)c*HW);
            float2 a2 = *(const float2*)(p2 + (long)c*HW);
            float2 a3 = *(const float2*)(p3 + (long)c*HW);
            ull x0 = pack2(fmaxf(a0.x,0.f), fmaxf(a0.y,0.f));
            ull x1 = pack2(fmaxf(a1.x,0.f), fmaxf(a1.y,0.f));
            ull x2 = pack2(fmaxf(a2.x,0.f), fmaxf(a2.y,0.f));
            ull x3 = pack2(fmaxf(a3.x,0.f), fmaxf(a3.y,0.f));
            const ull* wr = &sW[c*32 + og*8];
            #pragma unroll
            for (int oo = 0; oo < 8; oo++) {
                ull w = wr[oo];                 // broadcast LDS.64, feeds 4 FFMA2
                acc[oo]      = fma2(x0, w, acc[oo]);
                acc[8+oo]    = fma2(x1, w, acc[8+oo]);
                acc[16+oo]   = fma2(x2, w, acc[16+oo]);
                acc[24+oo]   = fma2(x3, w, acc[24+oo]);
            }
        }
        #pragma unroll
        for (int k = 0; k < 4; k++) {
            int w0 = 2*pg + (k & 1)*160;
            #pragma unroll
            for (int oo = 0; oo < 8; oo++) {
                int o = og*8 + oo;
                if (k < 2) *(ull*)&Ls[o*WW   + w0]      = acc[k*8 + oo];
                else       *(ull*)&RA[o*RSTR + w0 + 48] = acc[k*8 + oo];
            }
        }
    }
    __syncthreads();

    // ---- Phase 2: correlation. 640 tiles (160 w-pairs x 4 d-groups), 2/thread ----
    float* outp = out + ((long)b * DD * HH + h) * WW;
    for (int T = tid; T < 640; T += 320) {
        const int wp = T % 160;          // lanes consecutive in wp -> conflict-free
        const int ig = T / 160;          // 0..3
        const int i0 = ig * 12;
        const int w0 = 2 * wp;
        const int rbase = w0 + 36 - i0;  // RA index of V[0] (pair at e = -i0-12)

        ull acc[12];
        #pragma unroll
        for (int d = 0; d < 12; d++) acc[d] = 0ULL;

        for (int c = 0; c < 32; c++) {
            ull Lp = *(const ull*)&Ls[c*WW + w0];
            const float* rr = &RA[c*RSTR + rbase];
            ull V[7];
            #pragma unroll
            for (int j = 0; j < 7; j++) V[j] = *(const ull*)&rr[2*j];
            #pragma unroll
            for (int dp = 0; dp < 12; dp++) {
                ull v;
                if ((dp & 1) == 0) {
                    v = V[6 - dp/2];                      // aligned pair, e = -dp
                } else {
                    float2 va = *(float2*)&V[(11 - dp)/2]; // .y = R[w0-d]
                    float2 vb = *(float2*)&V[(13 - dp)/2]; // .x = R[w0+1-d]
                    v = pack2(va.y, vb.x);                 // ALU movs, no LDS
                }
                acc[dp] = fma2(Lp, v, acc[dp]);
            }
        }
        #pragma unroll
        for (int dp = 0; dp < 12; dp++) {
            float2 v = *(float2*)&acc[dp];
            v.x *= 0.03125f;   // mean over 32 channels
            v.y *= 0.03125f;
            *(float2*)&outp[(long)(i0 + dp)*HW + w0] = v;
        }
    }
}

// ---------------------------------------------------------------------------
extern "C" void kernel_launch(void* const* d_in, const int* in_sizes, int n_in,
                              void* d_out, int out_size)
{
    const float* fL = (const float*)d_in[0];
    const float* fR = (const float*)d_in[1];
    const float* bg = (const float*)d_in[2];
    const float* bb = (const float*)d_in[3];
    const float* bm = (const float*)d_in[4];
    const float* bv = (const float*)d_in[5];
    const float* cw = (const float*)d_in[6];
    const float* cb = (const float*)d_in[7];
    float* out = (float*)d_out;

    const int smem = 109824;
    cudaFuncSetAttribute(fused_kernel, cudaFuncAttributeMaxDynamicSharedMemorySize, smem);
    fused_kernel<<<BATCH*HH, 320, smem>>>(fL, fR, bg, bb, bm, bv, cw, cb, out);
}